// round 4
// baseline (speedup 1.0000x reference)
#include <cuda_runtime.h>
#include <cuda_bf16.h>

// Per-row loss scratch (8192 rows). __device__ global: allowed (no runtime alloc).
__device__ float g_row_loss[8192];

#define C_DIM 10000
#define B_DIM 8192
#define M_SCALE 4.0f
#define THREADS 256

// Kernel 1: one block per row. Single pass: S = sum(exp(x)).
// Then correct for the margin-scaled target logit and write per-row loss.
__global__ __launch_bounds__(THREADS) void ems_row_kernel(
    const float* __restrict__ inputs,
    const int* __restrict__ targets)   // JAX default: int32 despite jnp.int64 in source
{
    const int row = blockIdx.x;
    const int tid = threadIdx.x;
    const float4* __restrict__ rowp =
        reinterpret_cast<const float4*>(inputs + (size_t)row * C_DIM);
    const int n4 = C_DIM / 4;  // 2500; row stride 40000 B is 16B-aligned

    float s = 0.0f;
    // Strided float4 loop: ~10 iters/thread; independent loads give MLP>=4
    #pragma unroll 2
    for (int i = tid; i < n4; i += THREADS) {
        float4 v = __ldg(&rowp[i]);
        s += __expf(v.x);
        s += __expf(v.y);
        s += __expf(v.z);
        s += __expf(v.w);
    }

    // ---- block reduction ----
    #pragma unroll
    for (int off = 16; off > 0; off >>= 1)
        s += __shfl_xor_sync(0xFFFFFFFFu, s, off);

    __shared__ float warp_sums[THREADS / 32];
    const int lane = tid & 31, wid = tid >> 5;
    if (lane == 0) warp_sums[wid] = s;
    __syncthreads();

    if (wid == 0) {
        float t = (lane < THREADS / 32) ? warp_sums[lane] : 0.0f;
        #pragma unroll
        for (int off = 4; off > 0; off >>= 1)
            t += __shfl_xor_sync(0xFFFFFFFFu, t, off);
        if (lane == 0) {
            const int tgt = targets[row];
            const float xt = __ldg(inputs + (size_t)row * C_DIM + tgt);
            const float xtm = M_SCALE * xt;
            // replace exp(x_t) with exp(4*x_t) in the sum
            float sp = t - __expf(xt) + __expf(xtm);
            g_row_loss[row] = __logf(sp) - xtm;
        }
    }
}

// Kernel 2: deterministic reduction of 8192 per-row losses -> mean, into d_out.
__global__ __launch_bounds__(THREADS) void ems_reduce_kernel(float* __restrict__ out)
{
    const int tid = threadIdx.x;
    float s = 0.0f;
    #pragma unroll
    for (int i = tid; i < B_DIM; i += THREADS)
        s += g_row_loss[i];

    #pragma unroll
    for (int off = 16; off > 0; off >>= 1)
        s += __shfl_xor_sync(0xFFFFFFFFu, s, off);

    __shared__ float warp_sums[THREADS / 32];
    const int lane = tid & 31, wid = tid >> 5;
    if (lane == 0) warp_sums[wid] = s;
    __syncthreads();

    if (wid == 0) {
        float t = (lane < THREADS / 32) ? warp_sums[lane] : 0.0f;
        #pragma unroll
        for (int off = 4; off > 0; off >>= 1)
            t += __shfl_xor_sync(0xFFFFFFFFu, t, off);
        if (lane == 0)
            out[0] = t * (1.0f / (float)B_DIM);
    }
}

extern "C" void kernel_launch(void* const* d_in, const int* in_sizes, int n_in,
                              void* d_out, int out_size)
{
    const float* inputs = (const float*)d_in[0];
    const int* targets = (const int*)d_in[1];
    float* out = (float*)d_out;

    ems_row_kernel<<<B_DIM, THREADS>>>(inputs, targets);
    ems_reduce_kernel<<<1, THREADS>>>(out);
}

// round 6
// speedup vs baseline: 1.0391x; 1.0391x over previous
#include <cuda_runtime.h>
#include <cuda_bf16.h>

#define C_DIM   10000
#define B_DIM   8192
#define M_SCALE 4.0f
#define THREADS 256
#define N4      (C_DIM / 4)        // 2500 float4 per row
#define FULL_IT (N4 / THREADS)     // 9
#define TAIL_N  (N4 - FULL_IT * THREADS)  // 196

// Fixed-point (Q32) deterministic accumulator + completion counter.
__device__ unsigned long long g_acc  = 0ULL;
__device__ unsigned int       g_done = 0u;

__global__ __launch_bounds__(THREADS) void ems_fused_kernel(
    const float* __restrict__ inputs,
    const int* __restrict__ targets,   // int32 (JAX default int width)
    float* __restrict__ out)
{
    const int row = blockIdx.x;
    const int tid = threadIdx.x;
    const float4* __restrict__ rowp =
        reinterpret_cast<const float4*>(inputs + (size_t)row * C_DIM);

    // ---- front-batched loads: 9 full + predicated tail (MLP ~10) ----
    float4 v[FULL_IT];
    #pragma unroll
    for (int k = 0; k < FULL_IT; k++)
        v[k] = __ldg(&rowp[tid + k * THREADS]);

    const bool has_tail = (tid < TAIL_N);
    float4 vt = has_tail ? __ldg(&rowp[FULL_IT * THREADS + tid])
                         : make_float4(0.f, 0.f, 0.f, 0.f);

    // ---- exp + accumulate ----
    float s = 0.0f;
    #pragma unroll
    for (int k = 0; k < FULL_IT; k++) {
        s += __expf(v[k].x);
        s += __expf(v[k].y);
        s += __expf(v[k].z);
        s += __expf(v[k].w);
    }
    if (has_tail) {
        s += __expf(vt.x);
        s += __expf(vt.y);
        s += __expf(vt.z);
        s += __expf(vt.w);
    }

    // ---- block reduction ----
    #pragma unroll
    for (int off = 16; off > 0; off >>= 1)
        s += __shfl_xor_sync(0xFFFFFFFFu, s, off);

    __shared__ float warp_sums[THREADS / 32];
    const int lane = tid & 31, wid = tid >> 5;
    if (lane == 0) warp_sums[wid] = s;
    __syncthreads();

    if (wid == 0) {
        float t = (lane < THREADS / 32) ? warp_sums[lane] : 0.0f;
        #pragma unroll
        for (int off = 4; off > 0; off >>= 1)
            t += __shfl_xor_sync(0xFFFFFFFFu, t, off);

        if (lane == 0) {
            const int tgt = targets[row];
            const float xt  = __ldg(inputs + (size_t)row * C_DIM + tgt);
            const float xtm = M_SCALE * xt;
            // replace exp(x_t) by exp(4*x_t) in the row sum
            const float sp   = t - __expf(xt) + __expf(xtm);
            const float loss = __logf(sp) - xtm;

            // Deterministic fixed-point accumulate (Q32): integer adds commute.
            const long long q = __double2ll_rn((double)loss * 4294967296.0);
            atomicAdd(&g_acc, (unsigned long long)q);
            __threadfence();

            const unsigned int prev = atomicAdd(&g_done, 1u);
            if (prev == B_DIM - 1) {
                // All rows accumulated and visible (fence-before-count).
                const long long total = (long long)atomicAdd(&g_acc, 0ULL);
                out[0] = (float)((double)total * (1.0 / 4294967296.0) / (double)B_DIM);
                // Reset for the next graph replay (stream-ordered before it).
                atomicExch(&g_acc, 0ULL);
                atomicExch(&g_done, 0u);
            }
        }
    }
}

extern "C" void kernel_launch(void* const* d_in, const int* in_sizes, int n_in,
                              void* d_out, int out_size)
{
    const float* inputs = (const float*)d_in[0];
    const int* targets = (const int*)d_in[1];
    float* out = (float*)d_out;

    ems_fused_kernel<<<B_DIM, THREADS>>>(inputs, targets, out);
}